// round 11
// baseline (speedup 1.0000x reference)
#include <cuda_runtime.h>
#include <cuda_bf16.h>
#include <math.h>
#include <cstdint>

// Problem constants
#define BB 4
#define LL 2048
#define DMODEL 1024
#define HH 16
#define DD 64
#define MF 256          // random features
#define CC 128          // chunk size
#define NCH 16          // chunks per sequence
#define ROWS (BB*LL)    // 8192
#define BHL (BB*HH*LL)  // 131072
#define NBLK (BB*HH*NCH) // 1024

#define INV_SCALE 0.17677669529663687f   // 1 / 1024^0.25
#define CNORM 0.0625f                    // 256^-0.5
#define KEPS 1e-4f
#define NSTAB 1e-6f

// ---------------- PTX helpers (compute_103-safe) ----------------------------
__device__ __forceinline__ uint32_t smem_to_u32(const void* smem_ptr) {
    uint32_t addr;
    asm("{ .reg .u64 tmp; cvta.to.shared.u64 tmp, %1; cvt.u32.u64 %0, tmp; }"
        : "=r"(addr) : "l"(smem_ptr));
    return addr;
}
__device__ __forceinline__ void ldsm_x4(uint32_t* r, uint32_t addr) {
    asm volatile("ldmatrix.sync.aligned.m8n8.x4.shared.b16 {%0,%1,%2,%3}, [%4];"
        : "=r"(r[0]), "=r"(r[1]), "=r"(r[2]), "=r"(r[3]) : "r"(addr));
}
__device__ __forceinline__ void mma_bf16(float* c, const uint32_t* a, const uint32_t* b) {
    asm volatile(
        "mma.sync.aligned.m16n8k16.row.col.f32.bf16.bf16.f32 "
        "{%0,%1,%2,%3}, {%4,%5,%6,%7}, {%8,%9}, {%0,%1,%2,%3};"
        : "+f"(c[0]), "+f"(c[1]), "+f"(c[2]), "+f"(c[3])
        : "r"(a[0]), "r"(a[1]), "r"(a[2]), "r"(a[3]), "r"(b[0]), "r"(b[1]));
}
#define CP_ASYNC16(sm, gm) \
    asm volatile("cp.async.cg.shared.global [%0], [%1], 16;" :: "r"(sm), "l"(gm))
#define CP_COMMIT() asm volatile("cp.async.commit_group;" ::: "memory")
#define CP_WAIT1()  asm volatile("cp.async.wait_group 1;" ::: "memory")
#define CP_WAIT0()  asm volatile("cp.async.wait_group 0;" ::: "memory")

__device__ __forceinline__ void bf16split(float x, __nv_bfloat16& h, __nv_bfloat16& l) {
    h = __float2bfloat16(x);
    l = __float2bfloat16(x - __bfloat162float(h));
}

// ---------------- scratch (device globals; no allocations) ----------------
__device__ float g_vh[(size_t)BHL*DD];       // v heads (unscaled, fp32)
__device__ float g_hk[BHL];
__device__ float g_Ssum[(size_t)NBLK*MF*DD]; // per-chunk K'^T V, then exclusive prefix
__device__ float g_zsum[(size_t)NBLK*MF];    // per-chunk sum K', then exclusive prefix
__device__ float g_kstab;
// bf16 hi/lo planes
__device__ __nv_bfloat16 g_qhH[(size_t)BHL*DD];  // scaled q heads hi
__device__ __nv_bfloat16 g_qhL[(size_t)BHL*DD];  // scaled q heads lo
__device__ __nv_bfloat16 g_khH[(size_t)BHL*DD];  // scaled k heads hi
__device__ __nv_bfloat16 g_khL[(size_t)BHL*DD];  // scaled k heads lo
__device__ __nv_bfloat16 g_qphi[(size_t)BHL*MF];
__device__ __nv_bfloat16 g_qplo[(size_t)BHL*MF];
__device__ __nv_bfloat16 g_kphi[(size_t)BHL*MF];
__device__ __nv_bfloat16 g_kplo[(size_t)BHL*MF];
__device__ __nv_bfloat16 g_xhi[(size_t)3*ROWS*DMODEL];
__device__ __nv_bfloat16 g_xlo[(size_t)3*ROWS*DMODEL];
__device__ __nv_bfloat16 g_wthi[(size_t)4*DMODEL*DMODEL]; // W^T layout [N][K]
__device__ __nv_bfloat16 g_wtlo[(size_t)4*DMODEL*DMODEL];
__device__ __nv_bfloat16 g_rfthi[(size_t)MF*DD];          // RF^T [m][d]
__device__ __nv_bfloat16 g_rftlo[(size_t)MF*DD];
__device__ __nv_bfloat16 g_chi[(size_t)ROWS*DMODEL];      // ctx bf16 hi
__device__ __nv_bfloat16 g_clo[(size_t)ROWS*DMODEL];      // ctx bf16 lo

// ---------------- conversion kernels ---------------------------------------
__global__ void __launch_bounds__(256) convert_x_kernel(
    const float* __restrict__ q, const float* __restrict__ k, const float* __restrict__ v)
{
    const int z = blockIdx.z;
    if (z == 0 && blockIdx.x == 0 && threadIdx.x == 0)
        g_kstab = __int_as_float(0xff800000);
    const float* src = (z==0) ? q : (z==1) ? k : v;
    __nv_bfloat16* dh = g_xhi + (size_t)z*ROWS*DMODEL;
    __nv_bfloat16* dl = g_xlo + (size_t)z*ROWS*DMODEL;
    size_t i = ((size_t)blockIdx.x*256 + threadIdx.x) * 4;
    float4 x = *reinterpret_cast<const float4*>(&src[i]);
    __nv_bfloat16 h0,h1,h2,h3,l0,l1,l2,l3;
    bf16split(x.x,h0,l0); bf16split(x.y,h1,l1);
    bf16split(x.z,h2,l2); bf16split(x.w,h3,l3);
    __nv_bfloat162 hA{h0,h1}, hB{h2,h3}, lA{l0,l1}, lB{l2,l3};
    *reinterpret_cast<__nv_bfloat162*>(&dh[i])   = hA;
    *reinterpret_cast<__nv_bfloat162*>(&dh[i+2]) = hB;
    *reinterpret_cast<__nv_bfloat162*>(&dl[i])   = lA;
    *reinterpret_cast<__nv_bfloat162*>(&dl[i+2]) = lB;
}

__global__ void __launch_bounds__(1024) convert_wt_kernel(
    const float* __restrict__ Wq, const float* __restrict__ Wk,
    const float* __restrict__ Wv, const float* __restrict__ Wo)
{
    const int z = blockIdx.z;
    const float* W = (z==0)?Wq:(z==1)?Wk:(z==2)?Wv:Wo;
    __nv_bfloat16* dh = g_wthi + (size_t)z*DMODEL*DMODEL;
    __nv_bfloat16* dl = g_wtlo + (size_t)z*DMODEL*DMODEL;
    __shared__ float tile[32][33];
    int tx = threadIdx.x & 31, ty = threadIdx.x >> 5;
    int kk = blockIdx.y*32 + ty;
    int nn = blockIdx.x*32 + tx;
    tile[ty][tx] = W[(size_t)kk*DMODEL + nn];
    __syncthreads();
    float vv = tile[tx][ty];
    __nv_bfloat16 h, l;
    bf16split(vv, h, l);
    int n2 = blockIdx.x*32 + ty, k2 = blockIdx.y*32 + tx;
    dh[(size_t)n2*DMODEL + k2] = h;
    dl[(size_t)n2*DMODEL + k2] = l;
}

// RF [64][256] fp32 -> RF^T [256][64] bf16 hi/lo
__global__ void __launch_bounds__(1024) convert_rf_kernel(const float* __restrict__ RF)
{
    __shared__ float tile[32][33];
    int tx = threadIdx.x & 31, ty = threadIdx.x >> 5;
    int kk = blockIdx.y*32 + ty;   // d index
    int nn = blockIdx.x*32 + tx;   // m index
    tile[ty][tx] = RF[(size_t)kk*MF + nn];
    __syncthreads();
    float vv = tile[tx][ty];       // RF[by*32+tx][bx*32+ty]
    __nv_bfloat16 h, l;
    bf16split(vv, h, l);
    int n2 = blockIdx.x*32 + ty, k2 = blockIdx.y*32 + tx;
    g_rfthi[(size_t)n2*DD + k2] = h;
    g_rftlo[(size_t)n2*DD + k2] = l;
}

// ---------------- shared tile prefetch (cp.async), 128 rows x 32 bf16 ------
#define TSTRIDE 80          // bytes per smem row (32 bf16 + pad)
#define STAGE_BYTES 40960

__device__ __forceinline__ void pf_tile(
    uint32_t sm_off, const __nv_bfloat16* __restrict__ src,
    size_t rowbase, int k0, int tid, int srcstride)
{
    #pragma unroll
    for (int i = 0; i < 2; i++) {
        int u = i*256 + tid;
        int r = u >> 2, seg = u & 3;
        const __nv_bfloat16* gm = src + (rowbase + r)*srcstride + k0 + seg*8;
        CP_ASYNC16(sm_off + (uint32_t)(r*TSTRIDE + seg*16), gm);
    }
}

// ---------------- tensor-core GEMM via mma.sync (fp32 via bf16 hi/lo split) ----
__global__ void __launch_bounds__(256) tc_gemm_kernel(
    int mode,
    const float* __restrict__ bq, const float* __restrict__ bk,
    const float* __restrict__ bv, const float* __restrict__ bo,
    float* __restrict__ out)
{
    const int z = blockIdx.z;
    const __nv_bfloat16 *Xhi, *Xlo, *Whi, *Wlo;
    const float* bias;
    float scl = 1.0f;
    if (mode == 0) {
        Xhi = g_xhi + (size_t)z*ROWS*DMODEL; Xlo = g_xlo + (size_t)z*ROWS*DMODEL;
        Whi = g_wthi + (size_t)z*DMODEL*DMODEL; Wlo = g_wtlo + (size_t)z*DMODEL*DMODEL;
        bias = (z==0)?bq:(z==1)?bk:bv;
        scl = (z==2)?1.0f:INV_SCALE;
    } else {
        Xhi = g_chi; Xlo = g_clo;
        Whi = g_wthi + (size_t)3*DMODEL*DMODEL; Wlo = g_wtlo + (size_t)3*DMODEL*DMODEL;
        bias = bo;
    }
    const int row0 = blockIdx.y * 128;
    const int col0 = blockIdx.x * 128;
    const int tid = threadIdx.x;
    const int lane = tid & 31, wid = tid >> 5;
    const int warp_m = wid & 3;
    const int warp_n = wid >> 2;

    extern __shared__ __align__(16) char sgen[];
    const uint32_t sbase = smem_to_u32(sgen);

    float acc[2][8][4];
    #pragma unroll
    for (int mi = 0; mi < 2; mi++)
        #pragma unroll
        for (int nt = 0; nt < 8; nt++)
            #pragma unroll
            for (int e = 0; e < 4; e++) acc[mi][nt][e] = 0.f;

    const int a_row  = warp_m*32 + (lane & 15);
    const uint32_t a_koff = (uint32_t)((lane >> 4) * 16);
    const int b_row  = warp_n*64 + ((lane >> 4) << 3) + (lane & 7);
    const uint32_t b_koff = (uint32_t)(((lane >> 3) & 1) * 16);

    pf_tile(sbase + 0,     Xhi, row0, 0, tid, DMODEL);
    pf_tile(sbase + 10240, Xlo, row0, 0, tid, DMODEL);
    pf_tile(sbase + 20480, Whi, col0, 0, tid, DMODEL);
    pf_tile(sbase + 30720, Wlo, col0, 0, tid, DMODEL);
    CP_COMMIT();

    const int NSTEP = DMODEL / 32;
    for (int c = 0; c < NSTEP; c++) {
        const int s = c & 1;
        if (c + 1 < NSTEP) {
            const uint32_t so2 = sbase + (uint32_t)(s^1)*STAGE_BYTES;
            const int k0 = (c+1)*32;
            pf_tile(so2 + 0,     Xhi, row0, k0, tid, DMODEL);
            pf_tile(so2 + 10240, Xlo, row0, k0, tid, DMODEL);
            pf_tile(so2 + 20480, Whi, col0, k0, tid, DMODEL);
            pf_tile(so2 + 30720, Wlo, col0, k0, tid, DMODEL);
            CP_COMMIT();
            CP_WAIT1();
        } else {
            CP_WAIT0();
        }
        __syncthreads();

        const uint32_t st = sbase + (uint32_t)s*STAGE_BYTES;
        #pragma unroll
        for (int ks = 0; ks < 2; ks++) {
            const uint32_t kb = (uint32_t)(ks*32);
            uint32_t ah[2][4], al[2][4];
            #pragma unroll
            for (int mi = 0; mi < 2; mi++) {
                uint32_t arow_b = (uint32_t)((a_row + mi*16)*TSTRIDE) + kb + a_koff;
                ldsm_x4(ah[mi], st + 0     + arow_b);
                ldsm_x4(al[mi], st + 10240 + arow_b);
            }
            #pragma unroll
            for (int np = 0; np < 4; np++) {
                uint32_t bh[4], bl[4];
                uint32_t brow_b = (uint32_t)((b_row + np*16)*TSTRIDE) + kb + b_koff;
                ldsm_x4(bh, st + 20480 + brow_b);
                ldsm_x4(bl, st + 30720 + brow_b);
                #pragma unroll
                for (int mi = 0; mi < 2; mi++) {
                    mma_bf16(acc[mi][2*np],   ah[mi], bh);
                    mma_bf16(acc[mi][2*np],   ah[mi], bl);
                    mma_bf16(acc[mi][2*np],   al[mi], bh);
                    mma_bf16(acc[mi][2*np+1], ah[mi], bh+2);
                    mma_bf16(acc[mi][2*np+1], ah[mi], bl+2);
                    mma_bf16(acc[mi][2*np+1], al[mi], bh+2);
                }
            }
        }
        __syncthreads();
    }

    #pragma unroll
    for (int mi = 0; mi < 2; mi++) {
        #pragma unroll
        for (int half = 0; half < 2; half++) {
            const int r = row0 + warp_m*32 + mi*16 + (lane >> 2) + half*8;
            const int b_ = r >> 11, l_ = r & (LL-1);
            #pragma unroll
            for (int nt = 0; nt < 8; nt++) {
                const int cc = col0 + warp_n*64 + nt*8 + (lane & 3)*2;
                float2 bv2 = *reinterpret_cast<const float2*>(&bias[cc]);
                float x0 = acc[mi][nt][half*2+0] + bv2.x;
                float x1 = acc[mi][nt][half*2+1] + bv2.y;
                if (mode == 0) {
                    x0 *= scl; x1 *= scl;
                    const int h_ = cc >> 6, d_ = cc & 63;
                    const size_t off = (((size_t)b_*HH + h_)*LL + l_)*DD + d_;
                    if (z == 2) {
                        float2 o; o.x = x0; o.y = x1;
                        *reinterpret_cast<float2*>(&g_vh[off]) = o;
                    } else {
                        __nv_bfloat16 h0,h1,l0,l1;
                        bf16split(x0,h0,l0); bf16split(x1,h1,l1);
                        __nv_bfloat162 ph{h0,h1}, pl{l0,l1};
                        __nv_bfloat16* pH = (z==0) ? g_qhH : g_khH;
                        __nv_bfloat16* pL = (z==0) ? g_qhL : g_khL;
                        *reinterpret_cast<__nv_bfloat162*>(&pH[off]) = ph;
                        *reinterpret_cast<__nv_bfloat162*>(&pL[off]) = pl;
                    }
                } else {
                    float2 o; o.x = x0; o.y = x1;
                    *reinterpret_cast<float2*>(&out[(size_t)r*DMODEL + cc]) = o;
                }
            }
        }
    }
}

// ---------------- hk = -0.5*|ksc|^2 and global max (k_stab) ----------------
__device__ __forceinline__ void atomicMaxFloat(float* addr, float val) {
    if (val >= 0.f) atomicMax((int*)addr, __float_as_int(val));
    else            atomicMin((unsigned int*)addr, __float_as_uint(val));
}

__global__ void __launch_bounds__(256) hk_kernel()
{
    __shared__ float wmax[8];
    const int gw   = (blockIdx.x * 256 + threadIdx.x) >> 5;
    const int lane = threadIdx.x & 31;
    const __nv_bfloat16* hrow = g_khH + (size_t)gw * DD;
    const __nv_bfloat16* lrow = g_khL + (size_t)gw * DD;
    __nv_bfloat162 h2 = *reinterpret_cast<const __nv_bfloat162*>(&hrow[2*lane]);
    __nv_bfloat162 l2 = *reinterpret_cast<const __nv_bfloat162*>(&lrow[2*lane]);
    float a = __bfloat162float(h2.x) + __bfloat162float(l2.x);
    float b = __bfloat162float(h2.y) + __bfloat162float(l2.y);
    float s = a*a + b*b;
    #pragma unroll
    for (int o = 16; o > 0; o >>= 1) s += __shfl_xor_sync(0xffffffffu, s, o);
    float hv = -0.5f * s;
    if (lane == 0) { g_hk[gw] = hv; wmax[threadIdx.x >> 5] = hv; }
    __syncthreads();
    if (threadIdx.x == 0) {
        float mx = wmax[0];
        #pragma unroll
        for (int i = 1; i < 8; i++) mx = fmaxf(mx, wmax[i]);
        atomicMaxFloat(&g_kstab, mx);
    }
}

// ---------------- feature map via mma: exp(X @ RF) -> bf16 hi/lo planes -----
// X: 128 rows x 64 (bf16 hi/lo head planes); RF^T: 256 x 64 (bf16 hi/lo).
#define FA_ST 144
#define FB_ST 144
#define F_OFF_AH 0
#define F_OFF_AL 18432
#define F_OFF_BH 36864
#define F_OFF_BL 73728
#define FEAT_SMEM 110592

__global__ void __launch_bounds__(256) feat_mma_kernel()
{
    extern __shared__ __align__(16) char smf[];
    const uint32_t sb = smem_to_u32(smf);
    const int z = blockIdx.y;
    const size_t row0 = (size_t)blockIdx.x * 128;
    const __nv_bfloat16* AH = (z==0) ? g_qhH : g_khH;
    const __nv_bfloat16* AL = (z==0) ? g_qhL : g_khL;
    __nv_bfloat16* dsth = (z==0) ? g_qphi : g_kphi;
    __nv_bfloat16* dstl = (z==0) ? g_qplo : g_kplo;
    const int tid = threadIdx.x, lane = tid & 31, wid = tid >> 5;

    // load A (128x64) hi/lo
    #pragma unroll
    for (int i = 0; i < 4; i++) {
        int u = i*256 + tid;
        int r = u >> 3, seg = u & 7;
        CP_ASYNC16(sb + F_OFF_AH + (uint32_t)(r*FA_ST + seg*16), AH + (row0+r)*DD + seg*8);
        CP_ASYNC16(sb + F_OFF_AL + (uint32_t)(r*FA_ST + seg*16), AL + (row0+r)*DD + seg*8);
    }
    // load B = RF^T (256x64) hi/lo
    #pragma unroll
    for (int i = 0; i < 8; i++) {
        int u = i*256 + tid;
        int r = u >> 3, seg = u & 7;
        CP_ASYNC16(sb + F_OFF_BH + (uint32_t)(r*FB_ST + seg*16), g_rfthi + (size_t)r*DD + seg*8);
        CP_ASYNC16(sb + F_OFF_BL + (uint32_t)(r*FB_ST + seg*16), g_rftlo + (size_t)r*DD + seg*8);
    }
    CP_COMMIT(); CP_WAIT0();
    __syncthreads();

    const int arow = wid*16 + (lane & 15);
    const uint32_t akoff = (uint32_t)((lane >> 4) * 16);
    const int brow = ((lane >> 4) << 3) + (lane & 7);
    const uint32_t bkoff = (uint32_t)(((lane >> 3) & 1) * 16);

    const float kst = g_kstab;
    const int r0 = (int)row0 + wid*16 + (lane >> 2);
    const int r1 = r0 + 8;
    const float base0 = (z==1) ? (g_hk[r0] - kst) : 0.f;
    const float base1 = (z==1) ? (g_hk[r1] - kst) : 0.f;

    #pragma unroll
    for (int pass = 0; pass < 2; pass++) {
        float acc[16][4];
        #pragma unroll
        for (int nt = 0; nt < 16; nt++)
            #pragma unroll
            for (int e = 0; e < 4; e++) acc[nt][e] = 0.f;

        #pragma unroll
        for (int kstep = 0; kstep < 4; kstep++) {
            const uint32_t kb = (uint32_t)(kstep*32);
            uint32_t aH[4], aL[4];
            ldsm_x4(aH, sb + F_OFF_AH + (uint32_t)(arow*FA_ST) + akoff + kb);
            ldsm_x4(aL, sb + F_OFF_AL + (uint32_t)(arow*FA_ST) + akoff + kb);
            #pragma unroll
            for (int p = 0; p < 8; p++) {
                uint32_t bH[4], bL[4];
                uint32_t ro = (uint32_t)((16*(pass*8 + p) + brow)*FB_ST) + bkoff + kb;
                ldsm_x4(bH, sb + F_OFF_BH + ro);
                ldsm_x4(bL, sb + F_OFF_BL + ro);
                mma_bf16(acc[2*p],   aH, bH);
                mma_bf16(acc[2*p],   aH, bL);
                mma_bf16(acc[2*p],   aL, bH);
                mma_bf16(acc[2*p+1], aH, bH+2);
                mma_bf16(acc[2*p+1], aH, bL+2);
                mma_bf16(acc[2*p+1], aL, bH+2);
            }
        }
        // epilogue: exp + split + store
        #pragma unroll
        for (int nt = 0; nt < 16; nt++) {
            const int cc = pass*128 + nt*8 + (lane & 3)*2;
            float e0 = CNORM * (__expf(base0 + acc[nt][0]) + KEPS);
            float e1 = CNORM * (__expf(base0 + acc[nt][1]) + KEPS);
            float e2 = CNORM * (__expf(base1 + acc[nt][2]) + KEPS);
            float e3 = CNORM * (__expf(base1 + acc[nt][3]) + KEPS);
            __nv_bfloat16 h0,h1,h2,h3,l0,l1,l2,l3;
            bf16split(e0,h0,l0); bf16split(e1,h1,l1);
            bf16split(e2,h2,l2); bf16split(e3,h3,l3);
            __nv_bfloat162 ph0{h0,h1}, pl0{l0,l1}, ph1{h2,h3}, pl1{l2,l3};
            *reinterpret_cast<__nv_bfloat162*>(&dsth[(size_t)r0*MF + cc]) = ph0;
            *reinterpret_cast<__nv_bfloat162*>(&dstl[(size_t)r0*MF + cc]) = pl0;
            *reinterpret_cast<__nv_bfloat162*>(&dsth[(size_t)r1*MF + cc]) = ph1;
            *reinterpret_cast<__nv_bfloat162*>(&dstl[(size_t)r1*MF + cc]) = pl1;
        }
    }
}

// ---------------- chunk Ssum = K'^T V, zsum = sum K' ------------------------
__global__ void __launch_bounds__(256) chunk_kv_kernel()
{
    __shared__ float kp_s[32][256];
    __shared__ float v_s[32][64];
    const int blk = blockIdx.x;
    const int bh = blk >> 4, n = blk & 15;
    const size_t row0 = (size_t)bh * LL + n * CC;
    const int m = threadIdx.x;

    float acc[64];
    #pragma unroll
    for (int d = 0; d < 64; d++) acc[d] = 0.f;
    float zacc = 0.f;

    for (int j0 = 0; j0 < CC; j0 += 32) {
        #pragma unroll
        for (int it = 0; it < 8; it++) {
            int p = it*256 + m;
            int r = p >> 6, c4 = (p & 63) << 2;
            size_t off = (row0 + j0 + r)*MF + c4;
            __nv_bfloat162 h0 = *reinterpret_cast<const __nv_bfloat162*>(&g_kphi[off]);
            __nv_bfloat162 h1 = *reinterpret_cast<const __nv_bfloat162*>(&g_kphi[off+2]);
            __nv_bfloat162 l0 = *reinterpret_cast<const __nv_bfloat162*>(&g_kplo[off]);
            __nv_bfloat162 l1 = *reinterpret_cast<const __nv_bfloat162*>(&g_kplo[off+2]);
            float4 x;
            x.x = __bfloat162float(h0.x) + __bfloat162float(l0.x);
            x.y = __bfloat162float(h0.y) + __bfloat162float(l0.y);
            x.z = __bfloat162float(h1.x) + __bfloat162float(l1.x);
            x.w = __bfloat162float(h1.y) + __bfloat162float(l1.y);
            *reinterpret_cast<float4*>(&kp_s[r][c4]) = x;
        }
        #pragma unroll
        for (int it = 0; it < 2; it++) {
            int p = it*256 + m;
            int r = p >> 4, c4 = (p & 15) << 2;
            float4 x = *reinterpret_cast<const float4*>(&g_vh[(row0 + j0 + r)*DD + c4]);
            *reinterpret_cast<float4*>(&v_s[r][c4]) = x;
        }
        __syncthreads();
        #pragma unroll 4
        for (int jj = 0; jj < 32; jj++) {
            float kv = kp_s[jj][m];
            zacc += kv;
            const float4* vr = reinterpret_cast<const float4*>(&v_s[jj][0]);
            #pragma unroll
            for (int d4 = 0; d4 < 16; d4++) {
                float4 vv = vr[d4];
                acc[d4*4+0] = fmaf(kv, vv.x, acc[d4*4+0]);
                acc[d4*4+1] = fmaf(kv, vv.y, acc[d4*4+1]);
                acc[d4*4+2] = fmaf(kv, vv.z, acc[d4*4+2]);
                acc[d4*4+3] = fmaf(kv, vv.w, acc[d4*4+3]);
            }
        }
        __syncthreads();
    }
    size_t sbase = ((size_t)blk*MF + m)*DD;
    #pragma unroll
    for (int d4 = 0; d4 < 16; d4++) {
        float4 o;
        o.x = acc[d4*4+0]; o.y = acc[d4*4+1]; o.z = acc[d4*4+2]; o.w = acc[d4*4+3];
        *reinterpret_cast<float4*>(&g_Ssum[sbase + d4*4]) = o;
    }
    g_zsum[(size_t)blk*MF + m] = zacc;
}

// ---------------- exclusive prefix over the 16 chunks (in place) -----------
__global__ void __launch_bounds__(256) scan_kernel()
{
    const int idx = blockIdx.x * 256 + threadIdx.x;
    const int SMD = MF * DD;
    if (idx < BB*HH*SMD) {
        int bh = idx / SMD;
        int md = idx % SMD;
        size_t base = (size_t)bh * NCH * SMD + md;
        float run = 0.f;
        #pragma unroll
        for (int n = 0; n < NCH; n++) {
            size_t off = base + (size_t)n * SMD;
            float val = g_Ssum[off];
            g_Ssum[off] = run;
            run += val;
        }
    }
    if (idx < BB*HH*MF) {
        int bh = idx / MF, mm = idx % MF;
        size_t base = (size_t)bh * NCH * MF + mm;
        float run = 0.f;
        #pragma unroll
        for (int n = 0; n < NCH; n++) {
            size_t off = base + (size_t)n * MF;
            float val = g_zsum[off];
            g_zsum[off] = run;
            run += val;
        }
    }
}

// ---------------- chunk attention, all-mma ----------------------------------
#define AST 272
#define VST 272
#define QST 144
#define SST 144
#define OFF_AHI 0
#define OFF_ALO 34816
#define OFF_STG 69632
#define OFF_QHI OFF_STG
#define OFF_QLO (OFF_STG + 18432)
#define OFF_STHI (OFF_STG + 36864)
#define OFF_STLO (OFF_STG + 48384)
#define OFF_VTHI 151552
#define OFF_VTLO 173312
#define ATTN_SMEM 195072

__global__ void __launch_bounds__(256) chunk_attn_kernel()
{
    extern __shared__ __align__(16) char sm2[];
    const uint32_t sb = smem_to_u32(sm2);

    const int blk = blockIdx.x;
    const int bh = blk >> 4, n = blk & 15;
    const int b_ = bh >> 4, h_ = bh & 15;
    const size_t rowbase = (size_t)bh * LL + n * CC;
    const int tid = threadIdx.x;
    const int lane = tid & 31, wid = tid >> 5;
    const int wm = wid & 3, wn = wid >> 2;

    float acc[2][8][4];
    #pragma unroll
    for (int mi = 0; mi < 2; mi++)
        #pragma unroll
        for (int nt = 0; nt < 8; nt++)
            #pragma unroll
            for (int e = 0; e < 4; e++) acc[mi][nt][e] = 0.f;

    const int a_row  = wm*32 + (lane & 15);
    const uint32_t a_koff = (uint32_t)((lane >> 4) * 16);
    const int b_row  = wn*64 + ((lane >> 4) << 3) + (lane & 7);
    const uint32_t b_koff = (uint32_t)(((lane >> 3) & 1) * 16);

    pf_tile(sb + OFF_STG + 0,     g_qphi, rowbase, 0, tid, MF);
    pf_tile(sb + OFF_STG + 10240, g_qplo, rowbase, 0, tid, MF);
    pf_tile(sb + OFF_STG + 20480, g_kphi, rowbase, 0, tid, MF);
    pf_tile(sb + OFF_STG + 30720, g_kplo, rowbase, 0, tid, MF);
    CP_COMMIT();

    for (int c = 0; c < 8; c++) {
        const int s = c & 1;
        if (c < 7) {
            const uint32_t so2 = sb + OFF_STG + (uint32_t)(s^1)*STAGE_BYTES;
            const int k0 = (c+1)*32;
            pf_tile(so2 + 0,     g_qphi, rowbase, k0, tid, MF);
            pf_tile(so2 + 10240, g_qplo, rowbase, k0, tid, MF);
            pf_tile(so2 + 20480, g_kphi, rowbase, k0, tid, MF);
            pf_tile(so2 + 30720, g_kplo, rowbase, k0, tid, MF);
            CP_COMMIT();
            CP_WAIT1();
        } else {
            CP_WAIT0();
        }
        __syncthreads();

        const uint32_t st = sb + OFF_STG + (uint32_t)s*STAGE_BYTES;
        #pragma unroll
        for (int ks = 0; ks < 2; ks++) {
            const uint32_t kb = (uint32_t)(ks*32);
            uint32_t ah[2][4], al[2][4];
            #pragma unroll
            for (int mi = 0; mi < 2; mi++) {
                uint32_t arow_b = (uint32_t)((a_row + mi*16)*TSTRIDE) + kb + a_koff;
                ldsm_x4(ah[mi], st + 0     + arow_b);
                ldsm_x4(al[mi], st + 10240 + arow_b);
            }
            #pragma unroll
            for (int np = 0; np < 4; np++) {
                uint32_t bhr[4], blr[4];
                uint32_t brow_b = (uint32_t)((b_row + np*16)*TSTRIDE) + kb + b_koff;
                ldsm_x4(bhr, st + 20480 + brow_b);
                ldsm_x4(blr, st + 30720 + brow_b);
                #pragma unroll
                for (int mi = 0; mi < 2; mi++) {
                    mma_bf16(acc[mi][2*np],   ah[mi], bhr);
                    mma_bf16(acc[mi][2*np],   ah[mi], blr);
                    mma_bf16(acc[mi][2*np],   al[mi], bhr);
                    mma_bf16(acc[mi][2*np+1], ah[mi], bhr+2);
                    mma_bf16(acc[mi][2*np+1], ah[mi], blr+2);
                    mma_bf16(acc[mi][2*np+1], al[mi], bhr+2);
                }
            }
        }
        __syncthreads();
    }

    #pragma unroll
    for (int mi = 0; mi < 2; mi++) {
        #pragma unroll
        for (int nt = 0; nt < 8; nt++) {
            int gi0 = wm*32 + mi*16 + (lane >> 2);
            int gi1 = gi0 + 8;
            int gj  = wn*64 + nt*8 + (lane & 3)*2;
            float v0 = (gj   <= gi0) ? acc[mi][nt][0] : 0.f;
            float v1 = (gj+1 <= gi0) ? acc[mi][nt][1] : 0.f;
            float v2 = (gj   <= gi1) ? acc[mi][nt][2] : 0.f;
            float v3 = (gj+1 <= gi1) ? acc[mi][nt][3] : 0.f;
            __nv_bfloat16 h0,h1,h2,h3,l0,l1,l2,l3;
            bf16split(v0,h0,l0); bf16split(v1,h1,l1);
            bf16split(v2,h2,l2); bf16split(v3,h3,l3);
            __nv_bfloat162 ph0{h0,h1}, ph1{h2,h3}, pl0{l0,l1}, pl1{l2,l3};
            *reinterpret_cast<__nv_bfloat162*>(sm2 + OFF_AHI + gi0*AST + gj*2) = ph0;
            *reinterpret_cast<__nv_bfloat162*>(sm2 + OFF_AHI + gi1*AST + gj*2) = ph1;
            *reinterpret_cast<__nv_bfloat162*>(sm2 + OFF_ALO + gi0*AST + gj*2) = pl0;
            *reinterpret_cast<__nv_bfloat162*>(sm2 + OFF_ALO + gi1*AST + gj*2) = pl1;
        }
    }

    for (int u = tid; u < 128*64; u += 256) {
        int j = u >> 6, d = u & 63;
        float vv = g_vh[(rowbase + j)*DD + d];
        __nv_bfloat16 hh, ll;
        bf16split(vv, hh, ll);
        *reinterpret_cast<__nv_bfloat16*>(sm2 + OFF_VTHI + d*VST + j*2) = hh;
        *reinterpret_cast<__nv_bfloat16*>(sm2 + OFF_VTLO + d*VST + j*2) = ll;
    }
    if (tid < 128) {
        *reinterpret_cast<__nv_bfloat16*>(sm2 + OFF_VTHI + 64*VST + tid*2) = __float2bfloat16(1.0f);
        *reinterpret_cast<__nv_bfloat16*>(sm2 + OFF_VTLO + 64*VST + tid*2) = __float2bfloat16(0.0f);
    }
    for (int u = tid; u < 15*VST/4; u += 256) {
        *reinterpret_cast<float*>(sm2 + OFF_VTHI + 65*VST + u*4) = 0.f;
        *reinterpret_cast<float*>(sm2 + OFF_VTLO + 65*VST + u*4) = 0.f;
    }
    for (int u = tid; u < 15*SST/4; u += 256) {
        *reinterpret_cast<float*>(sm2 + OFF_STHI + 65*SST + u*4) = 0.f;
        *reinterpret_cast<float*>(sm2 + OFF_STLO + 65*SST + u*4) = 0.f;
    }
    __syncthreads();

    float acc2[9][4];
    #pragma unroll
    for (int nt = 0; nt < 9; nt++)
        #pragma unroll
        for (int e = 0; e < 4; e++) acc2[nt][e] = 0.f;

    const int arow2 = wid*16 + (lane & 15);
    const uint32_t akoff2 = (uint32_t)((lane >> 4) * 16);
    const int brow2 = ((lane >> 4) << 3) + (lane & 7);
    const uint32_t bkoff2 = (uint32_t)(((lane >> 3) & 1) * 16);

    #pragma unroll
    for (int kstep = 0; kstep < 8; kstep++) {
        const uint32_t kb = (uint32_t)(kstep*32);
        uint32_t aH[4], aL[4];
        ldsm_x4(aH, sb + OFF_AHI + (uint32_t)(arow2*AST) + akoff2 + kb);
        ldsm_x4(aL, sb + OFF_ALO + (uint32_t)(arow2*AST) + akoff2 + kb);
        #pragma unroll
        for (int p = 0; p < 5; p++) {
            uint32_t bH[4], bL[4];
            uint32_t ro = (uint32_t)((16*p + brow2)*VST) + bkoff2 + kb;
            ldsm_x4(bH, sb + OFF_VTHI + ro);
            ldsm_x4(bL, sb + OFF_VTLO + ro);
            #pragma unroll
            for (int t = 0; t < 2; t++) {
                int nt = 2*p + t;
                if (nt < 9) {
                    mma_bf16(acc2[nt], aH, bH + 2*t);
                    mma_bf16(acc2[nt], aH, bL + 2*t);
                    mma_bf16(acc2[nt], aL, bH + 2*t);
                }
            }
        }
    }

    for (int mt = 0; mt < MF; mt += 64) {
        __syncthreads();
        #pragma unroll
        for (int i = 0; i < 4; i++) {
            int u = i*256 + tid;
            int r = u >> 3, seg = u & 7;
            CP_ASYNC16(sb + OFF_QHI + (uint32_t)(r*QST + seg*16),
                       g_qphi + (rowbase + r)*MF + mt + seg*8);
            CP_ASYNC16(sb + OFF_QLO + (uint32_t)(r*QST + seg*16),
                       g_qplo + (rowbase + r)*MF + mt + seg*8);
        }
        CP_COMMIT();
        for (int u = tid; u < 64*64; u += 256) {
            int mm = u >> 6, d = u & 63;
            float sv = g_Ssum[((size_t)blk*MF + mt + mm)*DD + d];
            __nv_bfloat16 hh, ll;
            bf16split(sv, hh, ll);
            *reinterpret_cast<__nv_bfloat16*>(sm2 + OFF_STHI + d*SST + mm*2) = hh;
            *reinterpret_cast<__nv_bfloat16*>(sm2 + OFF_STLO + d*SST + mm*2) = ll;
        }
        if (tid < 64) {
            float zp = g_zsum[(size_t)blk*MF + mt + tid];
            __nv_bfloat16 hh, ll;
            bf16split(zp, hh, ll);
            *reinterpret_cast<__nv_bfloat16*>(sm2 + OFF_STHI + 64*SST + tid*2) = hh;
            *reinterpret_cast<__nv_bfloat16*>(sm2 + OFF_STLO + 64*SST + tid*2) = ll;
        }
        CP_WAIT0();
        __syncthreads();

        #pragma unroll
        for (int kstep = 0; kstep < 4; kstep++) {
            const uint32_t kb = (uint32_t)(kstep*32);
            uint32_t aH[4], aL[4];
            ldsm_x4(aH, sb + OFF_QHI + (uint32_t)(arow2*QST) + akoff2 + kb);
            ldsm_x4(aL, sb + OFF_QLO + (uint32_t)(arow2*QST) + akoff2 + kb);
            #pragma unroll
            for (int p = 0; p < 5; p++) {
                uint32_t bH[4], bL[4];
                uint32_t ro = (uint32_t)((16*p + brow2)*SST) + bkoff2 + kb;
                ldsm_x4(bH, sb + OFF_STHI + ro);
                ldsm_x4(bL, sb + OFF_STLO + ro);
                #pragma unroll
                for (int t = 0; t < 2; t++) {
                    int nt = 2*p + t;
                    if (nt < 9) {
                        mma_bf16(acc2[nt], aH, bH + 2*t);
                        mma_bf16(acc2[nt], aH, bL + 2*t);
                        mma_bf16(acc2[nt], aL, bH + 2*t);
                    }
                }
            }
        }
    }

    float d0 = __shfl_sync(0xffffffffu, acc2[8][0], lane & 28);
    float d1 = __shfl_sync(0xffffffffu, acc2[8][2], lane & 28);
    if (fabsf(d0) <= NSTAB) d0 += 2.0f*NSTAB;
    if (fabsf(d1) <= NSTAB) d1 += 2.0f*NSTAB;
    const float inv0 = 1.0f / d0;
    const float inv1 = 1.0f / d1;
    const int r0 = wid*16 + (lane >> 2);
    const int r1 = r0 + 8;
    const size_t ob = ((size_t)b_*LL + n*CC)*DMODEL + (size_t)h_*DD;
    #pragma unroll
    for (int nt = 0; nt < 8; nt++) {
        const int cc = nt*8 + (lane & 3)*2;
        float x0 = acc2[nt][0]*inv0, x1 = acc2[nt][1]*inv0;
        float y0 = acc2[nt][2]*inv1, y1 = acc2[nt][3]*inv1;
        __nv_bfloat16 h0,h1,h2,h3,l0,l1,l2,l3;
        bf16split(x0,h0,l0); bf16split(x1,h1,l1);
        bf16split(y0,h2,l2); bf16split(y1,h3,l3);
        __nv_bfloat162 ph0{h0,h1}, pl0{l0,l1}, ph1{h2,h3}, pl1{l2,l3};
        *reinterpret_cast<__nv_bfloat162*>(&g_chi[ob + (size_t)r0*DMODEL + cc]) = ph0;
        *reinterpret_cast<__nv_bfloat162*>(&g_clo[ob + (size_t)r0*DMODEL + cc]) = pl0;
        *reinterpret_cast<__nv_bfloat162*>(&g_chi[ob + (size_t)r1*DMODEL + cc]) = ph1;
        *reinterpret_cast<__nv_bfloat162*>(&g_clo[ob + (size_t)r1*DMODEL + cc]) = pl1;
    }
}

// ---------------- launch ---------------------------------------------------
extern "C" void kernel_launch(void* const* d_in, const int* in_sizes, int n_in,
                              void* d_out, int out_size)
{
    const float* q  = (const float*)d_in[0];
    const float* k  = (const float*)d_in[1];
    const float* v  = (const float*)d_in[2];
    const float* Wq = (const float*)d_in[3];
    const float* bq = (const float*)d_in[4];
    const float* Wk = (const float*)d_in[5];
    const float* bk = (const float*)d_in[6];
    const float* Wv = (const float*)d_in[7];
    const float* bv = (const float*)d_in[8];
    const float* Wo = (const float*)d_in[9];
    const float* bo = (const float*)d_in[10];
    const float* RF = (const float*)d_in[11];
    float* out = (float*)d_out;

    const size_t gsm = 2 * STAGE_BYTES;  // 81920B
    cudaFuncSetAttribute(tc_gemm_kernel, cudaFuncAttributeMaxDynamicSharedMemorySize, (int)gsm);
    cudaFuncSetAttribute(chunk_attn_kernel, cudaFuncAttributeMaxDynamicSharedMemorySize, ATTN_SMEM);
    cudaFuncSetAttribute(feat_mma_kernel, cudaFuncAttributeMaxDynamicSharedMemorySize, FEAT_SMEM);

    // bf16 hi/lo conversions (also inits k_stab)
    convert_x_kernel<<<dim3(ROWS*DMODEL/1024, 1, 3), 256>>>(q, k, v);
    convert_wt_kernel<<<dim3(32, 32, 4), 1024>>>(Wq, Wk, Wv, Wo);
    convert_rf_kernel<<<dim3(MF/32, DD/32), 1024>>>(RF);
    // QKV projections on tensor cores -> q/k bf16 hi/lo planes, v fp32
    tc_gemm_kernel<<<dim3(DMODEL/128, ROWS/128, 3), 256, gsm>>>(0, bq, bk, bv, bo, nullptr);
    // hk + global max (from bf16 planes)
    hk_kernel<<<BHL/8, 256>>>();
    // feature maps on tensor cores + __expf epilogue -> bf16 hi/lo planes
    feat_mma_kernel<<<dim3(BHL/128, 2), 256, FEAT_SMEM>>>();
    // per-chunk K'^T V and zsum
    chunk_kv_kernel<<<NBLK, 256>>>();
    // exclusive scan over chunks
    scan_kernel<<<(BB*HH*MF*DD)/256, 256>>>();
    // per-chunk causal attention (all-mma) -> ctx bf16 hi/lo
    chunk_attn_kernel<<<NBLK, 256, ATTN_SMEM>>>();
    // output projection on tensor cores
    tc_gemm_kernel<<<dim3(DMODEL/128, ROWS/128, 1), 256, gsm>>>(1, bq, bk, bv, bo, out);
}

// round 12
// speedup vs baseline: 1.0025x; 1.0025x over previous
#include <cuda_runtime.h>
#include <cuda_bf16.h>
#include <math.h>
#include <cstdint>

// Problem constants
#define BB 4
#define LL 2048
#define DMODEL 1024
#define HH 16
#define DD 64
#define MF 256          // random features
#define CC 128          // chunk size
#define NCH 16          // chunks per sequence
#define ROWS (BB*LL)    // 8192
#define BHL (BB*HH*LL)  // 131072
#define NBLK (BB*HH*NCH) // 1024

#define INV_SCALE 0.17677669529663687f   // 1 / 1024^0.25
#define CNORM 0.0625f                    // 256^-0.5
#define KEPS 1e-4f
#define NSTAB 1e-6f

// ---------------- PTX helpers (compute_103-safe) ----------------------------
__device__ __forceinline__ uint32_t smem_to_u32(const void* smem_ptr) {
    uint32_t addr;
    asm("{ .reg .u64 tmp; cvta.to.shared.u64 tmp, %1; cvt.u32.u64 %0, tmp; }"
        : "=r"(addr) : "l"(smem_ptr));
    return addr;
}
__device__ __forceinline__ void ldsm_x4(uint32_t* r, uint32_t addr) {
    asm volatile("ldmatrix.sync.aligned.m8n8.x4.shared.b16 {%0,%1,%2,%3}, [%4];"
        : "=r"(r[0]), "=r"(r[1]), "=r"(r[2]), "=r"(r[3]) : "r"(addr));
}
__device__ __forceinline__ void mma_bf16(float* c, const uint32_t* a, const uint32_t* b) {
    asm volatile(
        "mma.sync.aligned.m16n8k16.row.col.f32.bf16.bf16.f32 "
        "{%0,%1,%2,%3}, {%4,%5,%6,%7}, {%8,%9}, {%0,%1,%2,%3};"
        : "+f"(c[0]), "+f"(c[1]), "+f"(c[2]), "+f"(c[3])
        : "r"(a[0]), "r"(a[1]), "r"(a[2]), "r"(a[3]), "r"(b[0]), "r"(b[1]));
}
#define CP_ASYNC16(sm, gm) \
    asm volatile("cp.async.cg.shared.global [%0], [%1], 16;" :: "r"(sm), "l"(gm))
#define CP_COMMIT() asm volatile("cp.async.commit_group;" ::: "memory")
#define CP_WAIT1()  asm volatile("cp.async.wait_group 1;" ::: "memory")
#define CP_WAIT0()  asm volatile("cp.async.wait_group 0;" ::: "memory")

__device__ __forceinline__ void bf16split(float x, __nv_bfloat16& h, __nv_bfloat16& l) {
    h = __float2bfloat16(x);
    l = __float2bfloat16(x - __bfloat162float(h));
}

// ---------------- scratch (device globals; no allocations) ----------------
__device__ float g_vh[(size_t)BHL*DD];       // v heads (unscaled, fp32)
__device__ float g_hk[BHL];
__device__ float g_Ssum[(size_t)NBLK*MF*DD]; // per-chunk K'^T V, then exclusive prefix
__device__ float g_zsum[(size_t)NBLK*MF];    // per-chunk sum K', then exclusive prefix
__device__ float g_kstab;
// bf16 hi/lo planes
__device__ __nv_bfloat16 g_qhH[(size_t)BHL*DD];  // scaled q heads hi
__device__ __nv_bfloat16 g_qhL[(size_t)BHL*DD];  // scaled q heads lo
__device__ __nv_bfloat16 g_khH[(size_t)BHL*DD];  // scaled k heads hi
__device__ __nv_bfloat16 g_khL[(size_t)BHL*DD];  // scaled k heads lo
__device__ __nv_bfloat16 g_qphi[(size_t)BHL*MF];
__device__ __nv_bfloat16 g_qplo[(size_t)BHL*MF];
__device__ __nv_bfloat16 g_kphi[(size_t)BHL*MF];
__device__ __nv_bfloat16 g_kplo[(size_t)BHL*MF];
__device__ __nv_bfloat16 g_xhi[(size_t)3*ROWS*DMODEL];
__device__ __nv_bfloat16 g_xlo[(size_t)3*ROWS*DMODEL];
__device__ __nv_bfloat16 g_wthi[(size_t)4*DMODEL*DMODEL]; // W^T layout [N][K]
__device__ __nv_bfloat16 g_wtlo[(size_t)4*DMODEL*DMODEL];
__device__ __nv_bfloat16 g_rfthi[(size_t)MF*DD];          // RF^T [m][d]
__device__ __nv_bfloat16 g_rftlo[(size_t)MF*DD];
__device__ __nv_bfloat16 g_chi[(size_t)ROWS*DMODEL];      // ctx bf16 hi
__device__ __nv_bfloat16 g_clo[(size_t)ROWS*DMODEL];      // ctx bf16 lo

// ---------------- conversion kernels ---------------------------------------
__global__ void __launch_bounds__(256) convert_x_kernel(
    const float* __restrict__ q, const float* __restrict__ k, const float* __restrict__ v)
{
    const int z = blockIdx.z;
    if (z == 0 && blockIdx.x == 0 && threadIdx.x == 0)
        g_kstab = __int_as_float(0xff800000);
    const float* src = (z==0) ? q : (z==1) ? k : v;
    __nv_bfloat16* dh = g_xhi + (size_t)z*ROWS*DMODEL;
    __nv_bfloat16* dl = g_xlo + (size_t)z*ROWS*DMODEL;
    size_t i = ((size_t)blockIdx.x*256 + threadIdx.x) * 4;
    float4 x = *reinterpret_cast<const float4*>(&src[i]);
    __nv_bfloat16 h0,h1,h2,h3,l0,l1,l2,l3;
    bf16split(x.x,h0,l0); bf16split(x.y,h1,l1);
    bf16split(x.z,h2,l2); bf16split(x.w,h3,l3);
    __nv_bfloat162 hA{h0,h1}, hB{h2,h3}, lA{l0,l1}, lB{l2,l3};
    *reinterpret_cast<__nv_bfloat162*>(&dh[i])   = hA;
    *reinterpret_cast<__nv_bfloat162*>(&dh[i+2]) = hB;
    *reinterpret_cast<__nv_bfloat162*>(&dl[i])   = lA;
    *reinterpret_cast<__nv_bfloat162*>(&dl[i+2]) = lB;
}

__global__ void __launch_bounds__(1024) convert_wt_kernel(
    const float* __restrict__ Wq, const float* __restrict__ Wk,
    const float* __restrict__ Wv, const float* __restrict__ Wo)
{
    const int z = blockIdx.z;
    const float* W = (z==0)?Wq:(z==1)?Wk:(z==2)?Wv:Wo;
    __nv_bfloat16* dh = g_wthi + (size_t)z*DMODEL*DMODEL;
    __nv_bfloat16* dl = g_wtlo + (size_t)z*DMODEL*DMODEL;
    __shared__ float tile[32][33];
    int tx = threadIdx.x & 31, ty = threadIdx.x >> 5;
    int kk = blockIdx.y*32 + ty;
    int nn = blockIdx.x*32 + tx;
    tile[ty][tx] = W[(size_t)kk*DMODEL + nn];
    __syncthreads();
    float vv = tile[tx][ty];
    __nv_bfloat16 h, l;
    bf16split(vv, h, l);
    int n2 = blockIdx.x*32 + ty, k2 = blockIdx.y*32 + tx;
    dh[(size_t)n2*DMODEL + k2] = h;
    dl[(size_t)n2*DMODEL + k2] = l;
}

// RF [64][256] fp32 -> RF^T [256][64] bf16 hi/lo
__global__ void __launch_bounds__(1024) convert_rf_kernel(const float* __restrict__ RF)
{
    __shared__ float tile[32][33];
    int tx = threadIdx.x & 31, ty = threadIdx.x >> 5;
    int kk = blockIdx.y*32 + ty;   // d index
    int nn = blockIdx.x*32 + tx;   // m index
    tile[ty][tx] = RF[(size_t)kk*MF + nn];
    __syncthreads();
    float vv = tile[tx][ty];       // RF[by*32+tx][bx*32+ty]
    __nv_bfloat16 h, l;
    bf16split(vv, h, l);
    int n2 = blockIdx.x*32 + ty, k2 = blockIdx.y*32 + tx;
    g_rfthi[(size_t)n2*DD + k2] = h;
    g_rftlo[(size_t)n2*DD + k2] = l;
}

// ---------------- shared tile prefetch (cp.async), 128 rows x 32 bf16 ------
#define TSTRIDE 80          // bytes per smem row (32 bf16 + pad)
#define STAGE_BYTES 40960

__device__ __forceinline__ void pf_tile(
    uint32_t sm_off, const __nv_bfloat16* __restrict__ src,
    size_t rowbase, int k0, int tid, int srcstride)
{
    #pragma unroll
    for (int i = 0; i < 2; i++) {
        int u = i*256 + tid;
        int r = u >> 2, seg = u & 3;
        const __nv_bfloat16* gm = src + (rowbase + r)*srcstride + k0 + seg*8;
        CP_ASYNC16(sm_off + (uint32_t)(r*TSTRIDE + seg*16), gm);
    }
}

// ---------------- tensor-core GEMM via mma.sync (fp32 via bf16 hi/lo split) ----
__global__ void __launch_bounds__(256) tc_gemm_kernel(
    int mode,
    const float* __restrict__ bq, const float* __restrict__ bk,
    const float* __restrict__ bv, const float* __restrict__ bo,
    float* __restrict__ out)
{
    const int z = blockIdx.z;
    const __nv_bfloat16 *Xhi, *Xlo, *Whi, *Wlo;
    const float* bias;
    float scl = 1.0f;
    if (mode == 0) {
        Xhi = g_xhi + (size_t)z*ROWS*DMODEL; Xlo = g_xlo + (size_t)z*ROWS*DMODEL;
        Whi = g_wthi + (size_t)z*DMODEL*DMODEL; Wlo = g_wtlo + (size_t)z*DMODEL*DMODEL;
        bias = (z==0)?bq:(z==1)?bk:bv;
        scl = (z==2)?1.0f:INV_SCALE;
    } else {
        Xhi = g_chi; Xlo = g_clo;
        Whi = g_wthi + (size_t)3*DMODEL*DMODEL; Wlo = g_wtlo + (size_t)3*DMODEL*DMODEL;
        bias = bo;
    }
    const int row0 = blockIdx.y * 128;
    const int col0 = blockIdx.x * 128;
    const int tid = threadIdx.x;
    const int lane = tid & 31, wid = tid >> 5;
    const int warp_m = wid & 3;
    const int warp_n = wid >> 2;

    extern __shared__ __align__(16) char sgen[];
    const uint32_t sbase = smem_to_u32(sgen);

    float acc[2][8][4];
    #pragma unroll
    for (int mi = 0; mi < 2; mi++)
        #pragma unroll
        for (int nt = 0; nt < 8; nt++)
            #pragma unroll
            for (int e = 0; e < 4; e++) acc[mi][nt][e] = 0.f;

    const int a_row  = warp_m*32 + (lane & 15);
    const uint32_t a_koff = (uint32_t)((lane >> 4) * 16);
    const int b_row  = warp_n*64 + ((lane >> 4) << 3) + (lane & 7);
    const uint32_t b_koff = (uint32_t)(((lane >> 3) & 1) * 16);

    pf_tile(sbase + 0,     Xhi, row0, 0, tid, DMODEL);
    pf_tile(sbase + 10240, Xlo, row0, 0, tid, DMODEL);
    pf_tile(sbase + 20480, Whi, col0, 0, tid, DMODEL);
    pf_tile(sbase + 30720, Wlo, col0, 0, tid, DMODEL);
    CP_COMMIT();

    const int NSTEP = DMODEL / 32;
    for (int c = 0; c < NSTEP; c++) {
        const int s = c & 1;
        if (c + 1 < NSTEP) {
            const uint32_t so2 = sbase + (uint32_t)(s^1)*STAGE_BYTES;
            const int k0 = (c+1)*32;
            pf_tile(so2 + 0,     Xhi, row0, k0, tid, DMODEL);
            pf_tile(so2 + 10240, Xlo, row0, k0, tid, DMODEL);
            pf_tile(so2 + 20480, Whi, col0, k0, tid, DMODEL);
            pf_tile(so2 + 30720, Wlo, col0, k0, tid, DMODEL);
            CP_COMMIT();
            CP_WAIT1();
        } else {
            CP_WAIT0();
        }
        __syncthreads();

        const uint32_t st = sbase + (uint32_t)s*STAGE_BYTES;
        #pragma unroll
        for (int ks = 0; ks < 2; ks++) {
            const uint32_t kb = (uint32_t)(ks*32);
            uint32_t ah[2][4], al[2][4];
            #pragma unroll
            for (int mi = 0; mi < 2; mi++) {
                uint32_t arow_b = (uint32_t)((a_row + mi*16)*TSTRIDE) + kb + a_koff;
                ldsm_x4(ah[mi], st + 0     + arow_b);
                ldsm_x4(al[mi], st + 10240 + arow_b);
            }
            #pragma unroll
            for (int np = 0; np < 4; np++) {
                uint32_t bh[4], bl[4];
                uint32_t brow_b = (uint32_t)((b_row + np*16)*TSTRIDE) + kb + b_koff;
                ldsm_x4(bh, st + 20480 + brow_b);
                ldsm_x4(bl, st + 30720 + brow_b);
                #pragma unroll
                for (int mi = 0; mi < 2; mi++) {
                    mma_bf16(acc[mi][2*np],   ah[mi], bh);
                    mma_bf16(acc[mi][2*np],   ah[mi], bl);
                    mma_bf16(acc[mi][2*np],   al[mi], bh);
                    mma_bf16(acc[mi][2*np+1], ah[mi], bh+2);
                    mma_bf16(acc[mi][2*np+1], ah[mi], bl+2);
                    mma_bf16(acc[mi][2*np+1], al[mi], bh+2);
                }
            }
        }
        __syncthreads();
    }

    #pragma unroll
    for (int mi = 0; mi < 2; mi++) {
        #pragma unroll
        for (int half = 0; half < 2; half++) {
            const int r = row0 + warp_m*32 + mi*16 + (lane >> 2) + half*8;
            const int b_ = r >> 11, l_ = r & (LL-1);
            #pragma unroll
            for (int nt = 0; nt < 8; nt++) {
                const int cc = col0 + warp_n*64 + nt*8 + (lane & 3)*2;
                float2 bv2 = *reinterpret_cast<const float2*>(&bias[cc]);
                float x0 = acc[mi][nt][half*2+0] + bv2.x;
                float x1 = acc[mi][nt][half*2+1] + bv2.y;
                if (mode == 0) {
                    x0 *= scl; x1 *= scl;
                    const int h_ = cc >> 6, d_ = cc & 63;
                    const size_t off = (((size_t)b_*HH + h_)*LL + l_)*DD + d_;
                    if (z == 2) {
                        float2 o; o.x = x0; o.y = x1;
                        *reinterpret_cast<float2*>(&g_vh[off]) = o;
                    } else {
                        __nv_bfloat16 h0,h1,l0,l1;
                        bf16split(x0,h0,l0); bf16split(x1,h1,l1);
                        __nv_bfloat162 ph{h0,h1}, pl{l0,l1};
                        __nv_bfloat16* pH = (z==0) ? g_qhH : g_khH;
                        __nv_bfloat16* pL = (z==0) ? g_qhL : g_khL;
                        *reinterpret_cast<__nv_bfloat162*>(&pH[off]) = ph;
                        *reinterpret_cast<__nv_bfloat162*>(&pL[off]) = pl;
                    }
                } else {
                    float2 o; o.x = x0; o.y = x1;
                    *reinterpret_cast<float2*>(&out[(size_t)r*DMODEL + cc]) = o;
                }
            }
        }
    }
}

// ---------------- hk = -0.5*|ksc|^2 and global max (k_stab) ----------------
__device__ __forceinline__ void atomicMaxFloat(float* addr, float val) {
    if (val >= 0.f) atomicMax((int*)addr, __float_as_int(val));
    else            atomicMin((unsigned int*)addr, __float_as_uint(val));
}

__global__ void __launch_bounds__(256) hk_kernel()
{
    __shared__ float wmax[8];
    const int gw   = (blockIdx.x * 256 + threadIdx.x) >> 5;
    const int lane = threadIdx.x & 31;
    const __nv_bfloat16* hrow = g_khH + (size_t)gw * DD;
    const __nv_bfloat16* lrow = g_khL + (size_t)gw * DD;
    __nv_bfloat162 h2 = *reinterpret_cast<const __nv_bfloat162*>(&hrow[2*lane]);
    __nv_bfloat162 l2 = *reinterpret_cast<const __nv_bfloat162*>(&lrow[2*lane]);
    float a = __bfloat162float(h2.x) + __bfloat162float(l2.x);
    float b = __bfloat162float(h2.y) + __bfloat162float(l2.y);
    float s = a*a + b*b;
    #pragma unroll
    for (int o = 16; o > 0; o >>= 1) s += __shfl_xor_sync(0xffffffffu, s, o);
    float hv = -0.5f * s;
    if (lane == 0) { g_hk[gw] = hv; wmax[threadIdx.x >> 5] = hv; }
    __syncthreads();
    if (threadIdx.x == 0) {
        float mx = wmax[0];
        #pragma unroll
        for (int i = 1; i < 8; i++) mx = fmaxf(mx, wmax[i]);
        atomicMaxFloat(&g_kstab, mx);
    }
}

// ---------------- feature map via mma: exp(X @ RF) -> bf16 hi/lo planes -----
// X: 128 rows x 64 (bf16 hi/lo head planes); RF^T: 256 x 64 (bf16 hi/lo).
#define FA_ST 144
#define FB_ST 144
#define F_OFF_AH 0
#define F_OFF_AL 18432
#define F_OFF_BH 36864
#define F_OFF_BL 73728
#define FEAT_SMEM 110592

__global__ void __launch_bounds__(256) feat_mma_kernel()
{
    extern __shared__ __align__(16) char smf[];
    const uint32_t sb = smem_to_u32(smf);
    const int z = blockIdx.y;
    const size_t row0 = (size_t)blockIdx.x * 128;
    const __nv_bfloat16* AH = (z==0) ? g_qhH : g_khH;
    const __nv_bfloat16* AL = (z==0) ? g_qhL : g_khL;
    __nv_bfloat16* dsth = (z==0) ? g_qphi : g_kphi;
    __nv_bfloat16* dstl = (z==0) ? g_qplo : g_kplo;
    const int tid = threadIdx.x, lane = tid & 31, wid = tid >> 5;

    // load A (128x64) hi/lo
    #pragma unroll
    for (int i = 0; i < 4; i++) {
        int u = i*256 + tid;
        int r = u >> 3, seg = u & 7;
        CP_ASYNC16(sb + F_OFF_AH + (uint32_t)(r*FA_ST + seg*16), AH + (row0+r)*DD + seg*8);
        CP_ASYNC16(sb + F_OFF_AL + (uint32_t)(r*FA_ST + seg*16), AL + (row0+r)*DD + seg*8);
    }
    // load B = RF^T (256x64) hi/lo
    #pragma unroll
    for (int i = 0; i < 8; i++) {
        int u = i*256 + tid;
        int r = u >> 3, seg = u & 7;
        CP_ASYNC16(sb + F_OFF_BH + (uint32_t)(r*FB_ST + seg*16), g_rfthi + (size_t)r*DD + seg*8);
        CP_ASYNC16(sb + F_OFF_BL + (uint32_t)(r*FB_ST + seg*16), g_rftlo + (size_t)r*DD + seg*8);
    }
    CP_COMMIT(); CP_WAIT0();
    __syncthreads();

    const int arow = wid*16 + (lane & 15);
    const uint32_t akoff = (uint32_t)((lane >> 4) * 16);
    const int brow = ((lane >> 4) << 3) + (lane & 7);
    const uint32_t bkoff = (uint32_t)(((lane >> 3) & 1) * 16);

    const float kst = g_kstab;
    const int r0 = (int)row0 + wid*16 + (lane >> 2);
    const int r1 = r0 + 8;
    const float base0 = (z==1) ? (g_hk[r0] - kst) : 0.f;
    const float base1 = (z==1) ? (g_hk[r1] - kst) : 0.f;

    #pragma unroll
    for (int pass = 0; pass < 2; pass++) {
        float acc[16][4];
        #pragma unroll
        for (int nt = 0; nt < 16; nt++)
            #pragma unroll
            for (int e = 0; e < 4; e++) acc[nt][e] = 0.f;

        #pragma unroll
        for (int kstep = 0; kstep < 4; kstep++) {
            const uint32_t kb = (uint32_t)(kstep*32);
            uint32_t aH[4], aL[4];
            ldsm_x4(aH, sb + F_OFF_AH + (uint32_t)(arow*FA_ST) + akoff + kb);
            ldsm_x4(aL, sb + F_OFF_AL + (uint32_t)(arow*FA_ST) + akoff + kb);
            #pragma unroll
            for (int p = 0; p < 8; p++) {
                uint32_t bH[4], bL[4];
                uint32_t ro = (uint32_t)((16*(pass*8 + p) + brow)*FB_ST) + bkoff + kb;
                ldsm_x4(bH, sb + F_OFF_BH + ro);
                ldsm_x4(bL, sb + F_OFF_BL + ro);
                mma_bf16(acc[2*p],   aH, bH);
                mma_bf16(acc[2*p],   aH, bL);
                mma_bf16(acc[2*p],   aL, bH);
                mma_bf16(acc[2*p+1], aH, bH+2);
                mma_bf16(acc[2*p+1], aH, bL+2);
                mma_bf16(acc[2*p+1], aL, bH+2);
            }
        }
        // epilogue: exp + split + store
        #pragma unroll
        for (int nt = 0; nt < 16; nt++) {
            const int cc = pass*128 + nt*8 + (lane & 3)*2;
            float e0 = CNORM * (__expf(base0 + acc[nt][0]) + KEPS);
            float e1 = CNORM * (__expf(base0 + acc[nt][1]) + KEPS);
            float e2 = CNORM * (__expf(base1 + acc[nt][2]) + KEPS);
            float e3 = CNORM * (__expf(base1 + acc[nt][3]) + KEPS);
            __nv_bfloat16 h0,h1,h2,h3,l0,l1,l2,l3;
            bf16split(e0,h0,l0); bf16split(e1,h1,l1);
            bf16split(e2,h2,l2); bf16split(e3,h3,l3);
            __nv_bfloat162 ph0{h0,h1}, pl0{l0,l1}, ph1{h2,h3}, pl1{l2,l3};
            *reinterpret_cast<__nv_bfloat162*>(&dsth[(size_t)r0*MF + cc]) = ph0;
            *reinterpret_cast<__nv_bfloat162*>(&dstl[(size_t)r0*MF + cc]) = pl0;
            *reinterpret_cast<__nv_bfloat162*>(&dsth[(size_t)r1*MF + cc]) = ph1;
            *reinterpret_cast<__nv_bfloat162*>(&dstl[(size_t)r1*MF + cc]) = pl1;
        }
    }
}

// ---------------- chunk Ssum = K'^T V, zsum = sum K' ------------------------
__global__ void __launch_bounds__(256) chunk_kv_kernel()
{
    __shared__ float kp_s[32][256];
    __shared__ float v_s[32][64];
    const int blk = blockIdx.x;
    const int bh = blk >> 4, n = blk & 15;
    const size_t row0 = (size_t)bh * LL + n * CC;
    const int m = threadIdx.x;

    float acc[64];
    #pragma unroll
    for (int d = 0; d < 64; d++) acc[d] = 0.f;
    float zacc = 0.f;

    for (int j0 = 0; j0 < CC; j0 += 32) {
        #pragma unroll
        for (int it = 0; it < 8; it++) {
            int p = it*256 + m;
            int r = p >> 6, c4 = (p & 63) << 2;
            size_t off = (row0 + j0 + r)*MF + c4;
            __nv_bfloat162 h0 = *reinterpret_cast<const __nv_bfloat162*>(&g_kphi[off]);
            __nv_bfloat162 h1 = *reinterpret_cast<const __nv_bfloat162*>(&g_kphi[off+2]);
            __nv_bfloat162 l0 = *reinterpret_cast<const __nv_bfloat162*>(&g_kplo[off]);
            __nv_bfloat162 l1 = *reinterpret_cast<const __nv_bfloat162*>(&g_kplo[off+2]);
            float4 x;
            x.x = __bfloat162float(h0.x) + __bfloat162float(l0.x);
            x.y = __bfloat162float(h0.y) + __bfloat162float(l0.y);
            x.z = __bfloat162float(h1.x) + __bfloat162float(l1.x);
            x.w = __bfloat162float(h1.y) + __bfloat162float(l1.y);
            *reinterpret_cast<float4*>(&kp_s[r][c4]) = x;
        }
        #pragma unroll
        for (int it = 0; it < 2; it++) {
            int p = it*256 + m;
            int r = p >> 4, c4 = (p & 15) << 2;
            float4 x = *reinterpret_cast<const float4*>(&g_vh[(row0 + j0 + r)*DD + c4]);
            *reinterpret_cast<float4*>(&v_s[r][c4]) = x;
        }
        __syncthreads();
        #pragma unroll 4
        for (int jj = 0; jj < 32; jj++) {
            float kv = kp_s[jj][m];
            zacc += kv;
            const float4* vr = reinterpret_cast<const float4*>(&v_s[jj][0]);
            #pragma unroll
            for (int d4 = 0; d4 < 16; d4++) {
                float4 vv = vr[d4];
                acc[d4*4+0] = fmaf(kv, vv.x, acc[d4*4+0]);
                acc[d4*4+1] = fmaf(kv, vv.y, acc[d4*4+1]);
                acc[d4*4+2] = fmaf(kv, vv.z, acc[d4*4+2]);
                acc[d4*4+3] = fmaf(kv, vv.w, acc[d4*4+3]);
            }
        }
        __syncthreads();
    }
    size_t sbase = ((size_t)blk*MF + m)*DD;
    #pragma unroll
    for (int d4 = 0; d4 < 16; d4++) {
        float4 o;
        o.x = acc[d4*4+0]; o.y = acc[d4*4+1]; o.z = acc[d4*4+2]; o.w = acc[d4*4+3];
        *reinterpret_cast<float4*>(&g_Ssum[sbase + d4*4]) = o;
    }
    g_zsum[(size_t)blk*MF + m] = zacc;
}

// ---------------- exclusive prefix over the 16 chunks (in place) -----------
__global__ void __launch_bounds__(256) scan_kernel()
{
    const int idx = blockIdx.x * 256 + threadIdx.x;
    const int SMD = MF * DD;
    if (idx < BB*HH*SMD) {
        int bh = idx / SMD;
        int md = idx % SMD;
        size_t base = (size_t)bh * NCH * SMD + md;
        float run = 0.f;
        #pragma unroll
        for (int n = 0; n < NCH; n++) {
            size_t off = base + (size_t)n * SMD;
            float val = g_Ssum[off];
            g_Ssum[off] = run;
            run += val;
        }
    }
    if (idx < BB*HH*MF) {
        int bh = idx / MF, mm = idx % MF;
        size_t base = (size_t)bh * NCH * MF + mm;
        float run = 0.f;
        #pragma unroll
        for (int n = 0; n < NCH; n++) {
            size_t off = base + (size_t)n * MF;
            float val = g_zsum[off];
            g_zsum[off] = run;
            run += val;
        }
    }
}

// ---------------- chunk attention, all-mma ----------------------------------
#define AST 272
#define VST 272
#define QST 144
#define SST 144
#define OFF_AHI 0
#define OFF_ALO 34816
#define OFF_STG 69632
#define OFF_QHI OFF_STG
#define OFF_QLO (OFF_STG + 18432)
#define OFF_STHI (OFF_STG + 36864)
#define OFF_STLO (OFF_STG + 48384)
#define OFF_VTHI 151552
#define OFF_VTLO 173312
#define ATTN_SMEM 195072

__global__ void __launch_bounds__(256) chunk_attn_kernel()
{
    extern __shared__ __align__(16) char sm2[];
    const uint32_t sb = smem_to_u32(sm2);

    const int blk = blockIdx.x;
    const int bh = blk >> 4, n = blk & 15;
    const int b_ = bh >> 4, h_ = bh & 15;
    const size_t rowbase = (size_t)bh * LL + n * CC;
    const int tid = threadIdx.x;
    const int lane = tid & 31, wid = tid >> 5;
    const int wm = wid & 3, wn = wid >> 2;

    float acc[2][8][4];
    #pragma unroll
    for (int mi = 0; mi < 2; mi++)
        #pragma unroll
        for (int nt = 0; nt < 8; nt++)
            #pragma unroll
            for (int e = 0; e < 4; e++) acc[mi][nt][e] = 0.f;

    const int a_row  = wm*32 + (lane & 15);
    const uint32_t a_koff = (uint32_t)((lane >> 4) * 16);
    const int b_row  = wn*64 + ((lane >> 4) << 3) + (lane & 7);
    const uint32_t b_koff = (uint32_t)(((lane >> 3) & 1) * 16);

    pf_tile(sb + OFF_STG + 0,     g_qphi, rowbase, 0, tid, MF);
    pf_tile(sb + OFF_STG + 10240, g_qplo, rowbase, 0, tid, MF);
    pf_tile(sb + OFF_STG + 20480, g_kphi, rowbase, 0, tid, MF);
    pf_tile(sb + OFF_STG + 30720, g_kplo, rowbase, 0, tid, MF);
    CP_COMMIT();

    for (int c = 0; c < 8; c++) {
        const int s = c & 1;
        if (c < 7) {
            const uint32_t so2 = sb + OFF_STG + (uint32_t)(s^1)*STAGE_BYTES;
            const int k0 = (c+1)*32;
            pf_tile(so2 + 0,     g_qphi, rowbase, k0, tid, MF);
            pf_tile(so2 + 10240, g_qplo, rowbase, k0, tid, MF);
            pf_tile(so2 + 20480, g_kphi, rowbase, k0, tid, MF);
            pf_tile(so2 + 30720, g_kplo, rowbase, k0, tid, MF);
            CP_COMMIT();
            CP_WAIT1();
        } else {
            CP_WAIT0();
        }
        __syncthreads();

        const uint32_t st = sb + OFF_STG + (uint32_t)s*STAGE_BYTES;
        #pragma unroll
        for (int ks = 0; ks < 2; ks++) {
            const uint32_t kb = (uint32_t)(ks*32);
            uint32_t ah[2][4], al[2][4];
            #pragma unroll
            for (int mi = 0; mi < 2; mi++) {
                uint32_t arow_b = (uint32_t)((a_row + mi*16)*TSTRIDE) + kb + a_koff;
                ldsm_x4(ah[mi], st + 0     + arow_b);
                ldsm_x4(al[mi], st + 10240 + arow_b);
            }
            #pragma unroll
            for (int np = 0; np < 4; np++) {
                uint32_t bhr[4], blr[4];
                uint32_t brow_b = (uint32_t)((b_row + np*16)*TSTRIDE) + kb + b_koff;
                ldsm_x4(bhr, st + 20480 + brow_b);
                ldsm_x4(blr, st + 30720 + brow_b);
                #pragma unroll
                for (int mi = 0; mi < 2; mi++) {
                    mma_bf16(acc[mi][2*np],   ah[mi], bhr);
                    mma_bf16(acc[mi][2*np],   ah[mi], blr);
                    mma_bf16(acc[mi][2*np],   al[mi], bhr);
                    mma_bf16(acc[mi][2*np+1], ah[mi], bhr+2);
                    mma_bf16(acc[mi][2*np+1], ah[mi], blr+2);
                    mma_bf16(acc[mi][2*np+1], al[mi], bhr+2);
                }
            }
        }
        __syncthreads();
    }

    #pragma unroll
    for (int mi = 0; mi < 2; mi++) {
        #pragma unroll
        for (int nt = 0; nt < 8; nt++) {
            int gi0 = wm*32 + mi*16 + (lane >> 2);
            int gi1 = gi0 + 8;
            int gj  = wn*64 + nt*8 + (lane & 3)*2;
            float v0 = (gj   <= gi0) ? acc[mi][nt][0] : 0.f;
            float v1 = (gj+1 <= gi0) ? acc[mi][nt][1] : 0.f;
            float v2 = (gj   <= gi1) ? acc[mi][nt][2] : 0.f;
            float v3 = (gj+1 <= gi1) ? acc[mi][nt][3] : 0.f;
            __nv_bfloat16 h0,h1,h2,h3,l0,l1,l2,l3;
            bf16split(v0,h0,l0); bf16split(v1,h1,l1);
            bf16split(v2,h2,l2); bf16split(v3,h3,l3);
            __nv_bfloat162 ph0{h0,h1}, ph1{h2,h3}, pl0{l0,l1}, pl1{l2,l3};
            *reinterpret_cast<__nv_bfloat162*>(sm2 + OFF_AHI + gi0*AST + gj*2) = ph0;
            *reinterpret_cast<__nv_bfloat162*>(sm2 + OFF_AHI + gi1*AST + gj*2) = ph1;
            *reinterpret_cast<__nv_bfloat162*>(sm2 + OFF_ALO + gi0*AST + gj*2) = pl0;
            *reinterpret_cast<__nv_bfloat162*>(sm2 + OFF_ALO + gi1*AST + gj*2) = pl1;
        }
    }

    for (int u = tid; u < 128*64; u += 256) {
        int j = u >> 6, d = u & 63;
        float vv = g_vh[(rowbase + j)*DD + d];
        __nv_bfloat16 hh, ll;
        bf16split(vv, hh, ll);
        *reinterpret_cast<__nv_bfloat16*>(sm2 + OFF_VTHI + d*VST + j*2) = hh;
        *reinterpret_cast<__nv_bfloat16*>(sm2 + OFF_VTLO + d*VST + j*2) = ll;
    }
    if (tid < 128) {
        *reinterpret_cast<__nv_bfloat16*>(sm2 + OFF_VTHI + 64*VST + tid*2) = __float2bfloat16(1.0f);
        *reinterpret_cast<__nv_bfloat16*>(sm2 + OFF_VTLO + 64*VST + tid*2) = __float2bfloat16(0.0f);
    }
    for (int u = tid; u < 15*VST/4; u += 256) {
        *reinterpret_cast<float*>(sm2 + OFF_VTHI + 65*VST + u*4) = 0.f;
        *reinterpret_cast<float*>(sm2 + OFF_VTLO + 65*VST + u*4) = 0.f;
    }
    for (int u = tid; u < 15*SST/4; u += 256) {
        *reinterpret_cast<float*>(sm2 + OFF_STHI + 65*SST + u*4) = 0.f;
        *reinterpret_cast<float*>(sm2 + OFF_STLO + 65*SST + u*4) = 0.f;
    }
    __syncthreads();

    float acc2[9][4];
    #pragma unroll
    for (int nt = 0; nt < 9; nt++)
        #pragma unroll
        for (int e = 0; e < 4; e++) acc2[nt][e] = 0.f;

    const int arow2 = wid*16 + (lane & 15);
    const uint32_t akoff2 = (uint32_t)((lane >> 4) * 16);
    const int brow2 = ((lane >> 4) << 3) + (lane & 7);
    const uint32_t bkoff2 = (uint32_t)(((lane >> 3) & 1) * 16);

    #pragma unroll
    for (int kstep = 0; kstep < 8; kstep++) {
        const uint32_t kb = (uint32_t)(kstep*32);
        uint32_t aH[4], aL[4];
        ldsm_x4(aH, sb + OFF_AHI + (uint32_t)(arow2*AST) + akoff2 + kb);
        ldsm_x4(aL, sb + OFF_ALO + (uint32_t)(arow2*AST) + akoff2 + kb);
        #pragma unroll
        for (int p = 0; p < 5; p++) {
            uint32_t bH[4], bL[4];
            uint32_t ro = (uint32_t)((16*p + brow2)*VST) + bkoff2 + kb;
            ldsm_x4(bH, sb + OFF_VTHI + ro);
            ldsm_x4(bL, sb + OFF_VTLO + ro);
            #pragma unroll
            for (int t = 0; t < 2; t++) {
                int nt = 2*p + t;
                if (nt < 9) {
                    mma_bf16(acc2[nt], aH, bH + 2*t);
                    mma_bf16(acc2[nt], aH, bL + 2*t);
                    mma_bf16(acc2[nt], aL, bH + 2*t);
                }
            }
        }
    }

    for (int mt = 0; mt < MF; mt += 64) {
        __syncthreads();
        #pragma unroll
        for (int i = 0; i < 4; i++) {
            int u = i*256 + tid;
            int r = u >> 3, seg = u & 7;
            CP_ASYNC16(sb + OFF_QHI + (uint32_t)(r*QST + seg*16),
                       g_qphi + (rowbase + r)*MF + mt + seg*8);
            CP_ASYNC16(sb + OFF_QLO + (uint32_t)(r*QST + seg*16),
                       g_qplo + (rowbase + r)*MF + mt + seg*8);
        }
        CP_COMMIT();
        for (int u = tid; u < 64*64; u += 256) {
            int mm = u >> 6, d = u & 63;
            float sv = g_Ssum[((size_t)blk*MF + mt + mm)*DD + d];
            __nv_bfloat16 hh, ll;
            bf16split(sv, hh, ll);
            *reinterpret_cast<__nv_bfloat16*>(sm2 + OFF_STHI + d*SST + mm*2) = hh;
            *reinterpret_cast<__nv_bfloat16*>(sm2 + OFF_STLO + d*SST + mm*2) = ll;
        }
        if (tid < 64) {
            float zp = g_zsum[(size_t)blk*MF + mt + tid];
            __nv_bfloat16 hh, ll;
            bf16split(zp, hh, ll);
            *reinterpret_cast<__nv_bfloat16*>(sm2 + OFF_STHI + 64*SST + tid*2) = hh;
            *reinterpret_cast<__nv_bfloat16*>(sm2 + OFF_STLO + 64*SST + tid*2) = ll;
        }
        CP_WAIT0();
        __syncthreads();

        #pragma unroll
        for (int kstep = 0; kstep < 4; kstep++) {
            const uint32_t kb = (uint32_t)(kstep*32);
            uint32_t aH[4], aL[4];
            ldsm_x4(aH, sb + OFF_QHI + (uint32_t)(arow2*QST) + akoff2 + kb);
            ldsm_x4(aL, sb + OFF_QLO + (uint32_t)(arow2*QST) + akoff2 + kb);
            #pragma unroll
            for (int p = 0; p < 5; p++) {
                uint32_t bH[4], bL[4];
                uint32_t ro = (uint32_t)((16*p + brow2)*SST) + bkoff2 + kb;
                ldsm_x4(bH, sb + OFF_STHI + ro);
                ldsm_x4(bL, sb + OFF_STLO + ro);
                #pragma unroll
                for (int t = 0; t < 2; t++) {
                    int nt = 2*p + t;
                    if (nt < 9) {
                        mma_bf16(acc2[nt], aH, bH + 2*t);
                        mma_bf16(acc2[nt], aH, bL + 2*t);
                        mma_bf16(acc2[nt], aL, bH + 2*t);
                    }
                }
            }
        }
    }

    float d0 = __shfl_sync(0xffffffffu, acc2[8][0], lane & 28);
    float d1 = __shfl_sync(0xffffffffu, acc2[8][2], lane & 28);
    if (fabsf(d0) <= NSTAB) d0 += 2.0f*NSTAB;
    if (fabsf(d1) <= NSTAB) d1 += 2.0f*NSTAB;
    const float inv0 = 1.0f / d0;
    const float inv1 = 1.0f / d1;
    const int r0 = wid*16 + (lane >> 2);
    const int r1 = r0 + 8;
    const size_t ob = ((size_t)b_*LL + n*CC)*DMODEL + (size_t)h_*DD;
    #pragma unroll
    for (int nt = 0; nt < 8; nt++) {
        const int cc = nt*8 + (lane & 3)*2;
        float x0 = acc2[nt][0]*inv0, x1 = acc2[nt][1]*inv0;
        float y0 = acc2[nt][2]*inv1, y1 = acc2[nt][3]*inv1;
        __nv_bfloat16 h0,h1,h2,h3,l0,l1,l2,l3;
        bf16split(x0,h0,l0); bf16split(x1,h1,l1);
        bf16split(y0,h2,l2); bf16split(y1,h3,l3);
        __nv_bfloat162 ph0{h0,h1}, pl0{l0,l1}, ph1{h2,h3}, pl1{l2,l3};
        *reinterpret_cast<__nv_bfloat162*>(&g_chi[ob + (size_t)r0*DMODEL + cc]) = ph0;
        *reinterpret_cast<__nv_bfloat162*>(&g_clo[ob + (size_t)r0*DMODEL + cc]) = pl0;
        *reinterpret_cast<__nv_bfloat162*>(&g_chi[ob + (size_t)r1*DMODEL + cc]) = ph1;
        *reinterpret_cast<__nv_bfloat162*>(&g_clo[ob + (size_t)r1*DMODEL + cc]) = pl1;
    }
}

// ---------------- launch ---------------------------------------------------
extern "C" void kernel_launch(void* const* d_in, const int* in_sizes, int n_in,
                              void* d_out, int out_size)
{
    const float* q  = (const float*)d_in[0];
    const float* k  = (const float*)d_in[1];
    const float* v  = (const float*)d_in[2];
    const float* Wq = (const float*)d_in[3];
    const float* bq = (const float*)d_in[4];
    const float* Wk = (const float*)d_in[5];
    const float* bk = (const float*)d_in[6];
    const float* Wv = (const float*)d_in[7];
    const float* bv = (const float*)d_in[8];
    const float* Wo = (const float*)d_in[9];
    const float* bo = (const float*)d_in[10];
    const float* RF = (const float*)d_in[11];
    float* out = (float*)d_out;

    const size_t gsm = 2 * STAGE_BYTES;  // 81920B
    cudaFuncSetAttribute(tc_gemm_kernel, cudaFuncAttributeMaxDynamicSharedMemorySize, (int)gsm);
    cudaFuncSetAttribute(chunk_attn_kernel, cudaFuncAttributeMaxDynamicSharedMemorySize, ATTN_SMEM);
    cudaFuncSetAttribute(feat_mma_kernel, cudaFuncAttributeMaxDynamicSharedMemorySize, FEAT_SMEM);

    // bf16 hi/lo conversions (also inits k_stab)
    convert_x_kernel<<<dim3(ROWS*DMODEL/1024, 1, 3), 256>>>(q, k, v);
    convert_wt_kernel<<<dim3(32, 32, 4), 1024>>>(Wq, Wk, Wv, Wo);
    convert_rf_kernel<<<dim3(MF/32, DD/32), 1024>>>(RF);
    // QKV projections on tensor cores -> q/k bf16 hi/lo planes, v fp32
    tc_gemm_kernel<<<dim3(DMODEL/128, ROWS/128, 3), 256, gsm>>>(0, bq, bk, bv, bo, nullptr);
    // hk + global max (from bf16 planes)
    hk_kernel<<<BHL/8, 256>>>();
    // feature maps on tensor cores + __expf epilogue -> bf16 hi/lo planes
    feat_mma_kernel<<<dim3(BHL/128, 2), 256, FEAT_SMEM>>>();
    // per-chunk K'^T V and zsum
    chunk_kv_kernel<<<NBLK, 256>>>();
    // exclusive scan over chunks
    scan_kernel<<<(BB*HH*MF*DD)/256, 256>>>();
    // per-chunk causal attention (all-mma) -> ctx bf16 hi/lo
    chunk_attn_kernel<<<NBLK, 256, ATTN_SMEM>>>();
    // output projection on tensor cores
    tc_gemm_kernel<<<dim3(DMODEL/128, ROWS/128, 1), 256, gsm>>>(1, bq, bk, bv, bo, out);
}